// round 16
// baseline (speedup 1.0000x reference)
#include <cuda_runtime.h>
#include <cstdint>

#define BATCH   1024
#define TSTEPS  99
#define SEQ     100
#define HID     256
#define EMB     128
#define VOC     410
#define VOCP    448   // padded vocab for GEMM B tile

// ---------------- device scratch (static allocation: allowed) ----------------
__device__ __align__(16) float g_encgate[BATCH * HID * 4];         // 16 MB  [(b*256+j)*4+q]
__device__ __align__(16) float g_embgate[VOC * HID * 4];           // 1.6 MB [(v*256+j)*4+q]
__device__ __align__(16) float g_WpackHH[HID * HID * 4];           // 1 MB   [(k*256+j)*4+q]
__device__ __align__(16) float g_WpackIH_E[EMB * HID * 4];         // 0.5 MB [(e*256+j)*4+q]
__device__ __align__(16) float g_WpackIH_H[HID * HID * 4];         // 1 MB   [(h*256+j)*4+q]
__device__ __align__(16) float g_WencT[HID * HID];                 // 256 KB [k*256+h]
__device__ __align__(16) float g_WfcT[HID * VOCP];                 // 448 KB [k*448+v], zero padded
__device__ __align__(16) float g_hs[(size_t)BATCH * TSTEPS * HID]; // 104 MB [(b*99+t)*256+j]
__device__ int g_tok64;                                            // 1 = targets are int64

// ---------------- helpers ----------------
__device__ __forceinline__ void fma2(unsigned long long& d,
                                     unsigned long long a,
                                     unsigned long long b) {
    asm("fma.rn.f32x2 %0, %1, %2, %0;" : "+l"(d) : "l"(a), "l"(b));
}
__device__ __forceinline__ float2 unpack2(unsigned long long v) {
    float2 r;
    asm("mov.b64 {%0, %1}, %2;" : "=f"(r.x), "=f"(r.y) : "l"(v));
    return r;
}
__device__ __forceinline__ float sigf(float x) {
    return __fdividef(1.0f, 1.0f + __expf(-x));
}
__device__ __forceinline__ float tanhfast(float x) {
    return __fdividef(2.0f, 1.0f + __expf(-2.0f * x)) - 1.0f;
}

// ---------------- targets dtype detection (int32 vs int64) ----------------
__global__ void detect_tok_kernel(const void* __restrict__ tgt) {
    const long long* p = (const long long*)tgt;
    int ok = 1;
    for (int i = 0; i < 16; i++) {
        long long v = p[i];
        if (v < 0 || v >= VOC) ok = 0;
    }
    g_tok64 = ok;
}

// ---------------- one merged weight-packing kernel ----------------
#define N_WHH  (HID * HID)        // 65536
#define N_WIH  (384 * HID)        // 98304
#define N_WENC (HID * HID)        // 65536
#define N_WFC  (HID * VOCP)       // 114688
#define N_PACK (N_WHH + N_WIH + N_WENC + N_WFC)   // 344064

__global__ __launch_bounds__(256) void pack_all(const float* __restrict__ Whh,
                                                const float* __restrict__ Wih,
                                                const float* __restrict__ Wenc,
                                                const float* __restrict__ Wfc) {
    int i = blockIdx.x * 256 + threadIdx.x;
    if (i < N_WHH) {
        int k = i / HID, j = i % HID;
        float4 v;
        v.x = Whh[(0 * HID + j) * HID + k];
        v.y = Whh[(1 * HID + j) * HID + k];
        v.z = Whh[(2 * HID + j) * HID + k];
        v.w = Whh[(3 * HID + j) * HID + k];
        *(float4*)(g_WpackHH + (size_t)i * 4) = v;
        return;
    }
    i -= N_WHH;
    if (i < N_WIH) {
        int e = i / HID, j = i % HID;
        float4 v;
        v.x = Wih[(0 * HID + j) * 384 + e];
        v.y = Wih[(1 * HID + j) * 384 + e];
        v.z = Wih[(2 * HID + j) * 384 + e];
        v.w = Wih[(3 * HID + j) * 384 + e];
        if (e < EMB) *(float4*)(g_WpackIH_E + ((size_t)e * HID + j) * 4) = v;
        else         *(float4*)(g_WpackIH_H + ((size_t)(e - EMB) * HID + j) * 4) = v;
        return;
    }
    i -= N_WIH;
    if (i < N_WENC) {
        int k = i / HID, h = i % HID;
        g_WencT[i] = Wenc[h * HID + k];
        return;
    }
    i -= N_WENC;
    if (i < N_WFC) {
        int k = i / VOCP, v = i % VOCP;
        g_WfcT[i] = (v < VOC) ? Wfc[v * HID + k] : 0.0f;
    }
}

// ------- merged prologue: blocks 0..255  -> enc+encgate for 4 batch rows
//                           blocks 256..665 -> embgate for one vocab row -------
__global__ __launch_bounds__(256) void pre_kernel(const float* __restrict__ eo,
                                                  const float* __restrict__ benc,
                                                  const float* __restrict__ bih,
                                                  const float* __restrict__ bhh,
                                                  const float* __restrict__ emb) {
    __shared__ float xs[4][HID];
    __shared__ float es[4][HID];
    int j = threadIdx.x;
    int bid = blockIdx.x;

    if (bid >= BATCH / 4) {
        // ---- embgate path ----
        int v = bid - BATCH / 4;
        if (j < EMB) xs[0][j] = emb[(size_t)v * EMB + j];
        __syncthreads();
        float4 acc = make_float4(0.f, 0.f, 0.f, 0.f);
        for (int e = 0; e < EMB; e++) {
            float4 w = *(const float4*)(g_WpackIH_E + ((size_t)e * HID + j) * 4);
            float x = xs[0][e];
            acc.x += x * w.x; acc.y += x * w.y;
            acc.z += x * w.z; acc.w += x * w.w;
        }
        *(float4*)(g_embgate + ((size_t)v * HID + j) * 4) = acc;
        return;
    }

    // ---- enc + encgate path ----
    int b0 = bid * 4;
#pragma unroll
    for (int r = 0; r < 4; r++) xs[r][j] = eo[(size_t)(b0 + r) * HID + j];
    __syncthreads();
    {
        float a0 = 0.f, a1 = 0.f, a2 = 0.f, a3 = 0.f;
        for (int k = 0; k < HID; k++) {
            float w = g_WencT[k * HID + j];
            a0 += xs[0][k] * w; a1 += xs[1][k] * w;
            a2 += xs[2][k] * w; a3 += xs[3][k] * w;
        }
        float bb = benc[j];
        es[0][j] = a0 + bb; es[1][j] = a1 + bb;
        es[2][j] = a2 + bb; es[3][j] = a3 + bb;
    }
    __syncthreads();
    float4 acc[4];
#pragma unroll
    for (int r = 0; r < 4; r++) acc[r] = make_float4(0.f, 0.f, 0.f, 0.f);
    for (int h = 0; h < HID; h++) {
        float4 w = *(const float4*)(g_WpackIH_H + ((size_t)h * HID + j) * 4);
#pragma unroll
        for (int r = 0; r < 4; r++) {
            float x = es[r][h];
            acc[r].x += x * w.x; acc[r].y += x * w.y;
            acc[r].z += x * w.z; acc[r].w += x * w.w;
        }
    }
    float4 bias;
    bias.x = bih[0 * HID + j] + bhh[0 * HID + j];
    bias.y = bih[1 * HID + j] + bhh[1 * HID + j];
    bias.z = bih[2 * HID + j] + bhh[2 * HID + j];
    bias.w = bih[3 * HID + j] + bhh[3 * HID + j];
#pragma unroll
    for (int r = 0; r < 4; r++) {
        float4 o = acc[r];
        o.x += bias.x; o.y += bias.y; o.z += bias.z; o.w += bias.w;
        *(float4*)(g_encgate + ((size_t)(b0 + r) * HID + j) * 4) = o;
    }
}

// ---------------- the recurrence: 99 LSTM steps, 8 rows / block, 512 threads ----------------
// k-loop start rotated per block (koff) to decorrelate the chip-wide weight
// stream across L2 slices (slice-camping fix). h is fully resident in smem,
// so any k-order is valid.
#define HSTRIDE 20
__global__ __launch_bounds__(512, 1) void lstm_kernel(const void* __restrict__ tgt) {
    __shared__ __align__(16) float h_dup[HID * HSTRIDE];   // 20 KB
    int tid = threadIdx.x;
    int j   = tid & 255;
    int rg  = tid >> 8;          // 0/1: row group
    int b0  = blockIdx.x * 8;
    int lane = tid & 31;
    const int koff = (blockIdx.x * 2) & 255;
    const int tok64 = g_tok64;
    const long long* t64 = (const long long*)tgt;
    const int*       t32 = (const int*)tgt;

    float4 ev[4];
#pragma unroll
    for (int r = 0; r < 4; r++)
        ev[r] = *(const float4*)(g_encgate + ((size_t)(b0 + rg * 4 + r) * HID + j) * 4);

    float c[4] = {0.f, 0.f, 0.f, 0.f};
    for (int i = tid; i < HID * HSTRIDE; i += 512) h_dup[i] = 0.0f;
    __syncthreads();

    const ulonglong2* Wp = (const ulonglong2*)g_WpackHH;

    for (int t = 0; t < TSTEPS; t++) {
        int myTok = 0;
        if (lane < 8) {
            size_t idx = (size_t)(b0 + lane) * SEQ + t;
            myTok = tok64 ? (int)t64[idx] : t32[idx];
        }
        int tok[4];
#pragma unroll
        for (int r = 0; r < 4; r++) tok[r] = __shfl_sync(0xffffffffu, myTok, rg * 4 + r);

        float4 gx[4];
#pragma unroll
        for (int r = 0; r < 4; r++)
            gx[r] = *(const float4*)(g_embgate + ((size_t)tok[r] * HID + j) * 4);

        unsigned long long acc[4][2];
#pragma unroll
        for (int r = 0; r < 4; r++) { acc[r][0] = 0ull; acc[r][1] = 0ull; }

#pragma unroll 8
        for (int kk = 0; kk < HID; kk++) {
            int k = (kk + koff) & 255;                     // per-block rotation
            ulonglong2 wv = Wp[k * HID + j];               // (w_i,w_f),(w_g,w_o)
            const ulonglong2* hp = (const ulonglong2*)(h_dup + k * HSTRIDE + rg * 8);
            ulonglong2 h01 = hp[0], h23 = hp[1];
            fma2(acc[0][0], h01.x, wv.x); fma2(acc[0][1], h01.x, wv.y);
            fma2(acc[1][0], h01.y, wv.x); fma2(acc[1][1], h01.y, wv.y);
            fma2(acc[2][0], h23.x, wv.x); fma2(acc[2][1], h23.x, wv.y);
            fma2(acc[3][0], h23.y, wv.x); fma2(acc[3][1], h23.y, wv.y);
        }

        float hv[4];
#pragma unroll
        for (int r = 0; r < 4; r++) {
            float2 if_ = unpack2(acc[r][0]);
            float2 go  = unpack2(acc[r][1]);
            float xi = if_.x + gx[r].x + ev[r].x;
            float xf = if_.y + gx[r].y + ev[r].y;
            float xg = go.x  + gx[r].z + ev[r].z;
            float xo = go.y  + gx[r].w + ev[r].w;
            float ii = sigf(xi), ff = sigf(xf);
            float gg = tanhfast(xg), oo = sigf(xo);
            c[r] = ff * c[r] + ii * gg;
            hv[r] = oo * tanhfast(c[r]);
        }
        __syncthreads();   // all reads of h_dup (step t) complete
        {
            float4 w0 = make_float4(hv[0], hv[0], hv[1], hv[1]);
            float4 w1 = make_float4(hv[2], hv[2], hv[3], hv[3]);
            float* base = h_dup + j * HSTRIDE + rg * 8;
            *(float4*)(base)     = w0;
            *(float4*)(base + 4) = w1;
#pragma unroll
            for (int r = 0; r < 4; r++)
                g_hs[((size_t)(b0 + rg * 4 + r) * TSTEPS + t) * HID + j] = hv[r];
        }
        __syncthreads();   // new h visible for step t+1
    }
}

// ---------------- logits = hs @ W_fc^T + b_fc  (M=101376, N=410, K=256) ----------------
#define GM 128
#define GN 64
#define GK 16
__global__ __launch_bounds__(256) void logits_gemm(const float* __restrict__ bfc,
                                                   float* __restrict__ out) {
    __shared__ __align__(16) float As[GK * GM * 2];  // [kk][m*2] duplicated, 16 KB
    __shared__ __align__(16) float Bs[GK * GN];      // [kk][n], 4 KB
    int tid = threadIdx.x;
    int tx = tid & 15;     // n group (4 cols)
    int ty = tid >> 4;     // m group (8 rows)
    size_t row0 = (size_t)blockIdx.x * GM;
    int n0 = blockIdx.y * GN;

    unsigned long long acc[8][2];
#pragma unroll
    for (int m = 0; m < 8; m++) { acc[m][0] = 0ull; acc[m][1] = 0ull; }

    for (int k0 = 0; k0 < HID; k0 += GK) {
#pragma unroll
        for (int l = 0; l < 2; l++) {
            int idx = tid + l * 256;       // 0..511
            int r  = idx >> 2;             // 0..127
            int kq = idx & 3;              // 0..3
            float4 v = *(const float4*)(g_hs + (row0 + r) * HID + k0 + kq * 4);
            int kk = kq * 4;
            As[(kk + 0) * 2 * GM + r * 2] = v.x; As[(kk + 0) * 2 * GM + r * 2 + 1] = v.x;
            As[(kk + 1) * 2 * GM + r * 2] = v.y; As[(kk + 1) * 2 * GM + r * 2 + 1] = v.y;
            As[(kk + 2) * 2 * GM + r * 2] = v.z; As[(kk + 2) * 2 * GM + r * 2 + 1] = v.z;
            As[(kk + 3) * 2 * GM + r * 2] = v.w; As[(kk + 3) * 2 * GM + r * 2 + 1] = v.w;
        }
        {
            int kk = tid >> 4;
            int nq = tid & 15;
            float4 bv = *(const float4*)(g_WfcT + (size_t)(k0 + kk) * VOCP + n0 + nq * 4);
            *(float4*)(Bs + kk * GN + nq * 4) = bv;
        }
        __syncthreads();
#pragma unroll
        for (int kk = 0; kk < GK; kk++) {
            const ulonglong2* ap = (const ulonglong2*)(As + kk * 2 * GM + ty * 16);
            ulonglong2 a01 = ap[0], a23 = ap[1], a45 = ap[2], a67 = ap[3];
            ulonglong2 bb = *(const ulonglong2*)(Bs + kk * GN + tx * 4);
            fma2(acc[0][0], a01.x, bb.x); fma2(acc[0][1], a01.x, bb.y);
            fma2(acc[1][0], a01.y, bb.x); fma2(acc[1][1], a01.y, bb.y);
            fma2(acc[2][0], a23.x, bb.x); fma2(acc[2][1], a23.x, bb.y);
            fma2(acc[3][0], a23.y, bb.x); fma2(acc[3][1], a23.y, bb.y);
            fma2(acc[4][0], a45.x, bb.x); fma2(acc[4][1], a45.x, bb.y);
            fma2(acc[5][0], a45.y, bb.x); fma2(acc[5][1], a45.y, bb.y);
            fma2(acc[6][0], a67.x, bb.x); fma2(acc[6][1], a67.x, bb.y);
            fma2(acc[7][0], a67.y, bb.x); fma2(acc[7][1], a67.y, bb.y);
        }
        __syncthreads();
    }

    int n = n0 + tx * 4;
    float b0v = (n + 0 < VOC) ? bfc[n + 0] : 0.f;
    float b1v = (n + 1 < VOC) ? bfc[n + 1] : 0.f;
    float b2v = (n + 2 < VOC) ? bfc[n + 2] : 0.f;
    float b3v = (n + 3 < VOC) ? bfc[n + 3] : 0.f;
#pragma unroll
    for (int m = 0; m < 8; m++) {
        size_t row = row0 + (size_t)ty * 8 + m;
        float2 v01 = unpack2(acc[m][0]);
        float2 v23 = unpack2(acc[m][1]);
        float* op = out + row * VOC + n;
        if (n + 0 < VOC) op[0] = v01.x + b0v;
        if (n + 1 < VOC) op[1] = v01.y + b1v;
        if (n + 2 < VOC) op[2] = v23.x + b2v;
        if (n + 3 < VOC) op[3] = v23.y + b3v;
    }
}

// ---------------- launch ----------------
extern "C" void kernel_launch(void* const* d_in, const int* in_sizes, int n_in,
                              void* d_out, int out_size) {
    const float* encoder_out = (const float*)d_in[0];
    const void*  targets     = (const void*)d_in[1];
    const float* emb         = (const float*)d_in[2];
    const float* W_enc       = (const float*)d_in[3];
    const float* b_enc       = (const float*)d_in[4];
    const float* W_ih        = (const float*)d_in[5];
    const float* W_hh        = (const float*)d_in[6];
    const float* b_ih        = (const float*)d_in[7];
    const float* b_hh        = (const float*)d_in[8];
    const float* W_fc        = (const float*)d_in[9];
    const float* b_fc        = (const float*)d_in[10];
    float* out = (float*)d_out;

    detect_tok_kernel<<<1, 1>>>(targets);                                   // launch 1
    pack_all<<<(N_PACK + 255) / 256, 256>>>(W_hh, W_ih, W_enc, W_fc);       // launch 2
    pre_kernel<<<BATCH / 4 + VOC, 256>>>(encoder_out, b_enc, b_ih, b_hh, emb); // launch 3
    lstm_kernel<<<BATCH / 8, 512>>>(targets);                               // launch 4 (ncu target)
    dim3 grid((BATCH * TSTEPS) / GM, (VOCP + GN - 1) / GN);                 // (792, 7)
    logits_gemm<<<grid, 256>>>(b_fc, out);                                  // launch 5
}

// round 17
// speedup vs baseline: 1.2066x; 1.2066x over previous
#include <cuda_runtime.h>
#include <cstdint>

#define BATCH   1024
#define TSTEPS  99
#define SEQ     100
#define HID     256
#define EMB     128
#define VOC     410
#define VOCP    448   // padded vocab for GEMM B tile

// ---------------- device scratch (static allocation: allowed) ----------------
__device__ __align__(16) float g_encgate[BATCH * HID * 4];         // 16 MB  [(b*256+j)*4+q]
__device__ __align__(16) float g_embgate[VOC * HID * 4];           // 1.6 MB [(v*256+j)*4+q]
__device__ __align__(16) float g_WpackHH[HID * HID * 4];           // 1 MB   [(k*256+j)*4+q]
__device__ __align__(16) float g_WpackIH_E[EMB * HID * 4];         // 0.5 MB [(e*256+j)*4+q]
__device__ __align__(16) float g_WpackIH_H[HID * HID * 4];         // 1 MB   [(h*256+j)*4+q]
__device__ __align__(16) float g_WencT[HID * HID];                 // 256 KB [k*256+h]
__device__ __align__(16) float g_WfcT[HID * VOCP];                 // 448 KB [k*448+v], zero padded
__device__ __align__(16) float g_hs[(size_t)BATCH * TSTEPS * HID]; // 104 MB [(b*99+t)*256+j]
__device__ int g_tok64;                                            // 1 = targets are int64

// ---------------- helpers ----------------
__device__ __forceinline__ void fma2(unsigned long long& d,
                                     unsigned long long a,
                                     unsigned long long b) {
    asm("fma.rn.f32x2 %0, %1, %2, %0;" : "+l"(d) : "l"(a), "l"(b));
}
__device__ __forceinline__ void add2(unsigned long long& d, unsigned long long a) {
    asm("add.rn.f32x2 %0, %0, %1;" : "+l"(d) : "l"(a));
}
__device__ __forceinline__ float2 unpack2(unsigned long long v) {
    float2 r;
    asm("mov.b64 {%0, %1}, %2;" : "=f"(r.x), "=f"(r.y) : "l"(v));
    return r;
}
__device__ __forceinline__ float sigf(float x) {
    return __fdividef(1.0f, 1.0f + __expf(-x));
}
__device__ __forceinline__ float tanhfast(float x) {
    return __fdividef(2.0f, 1.0f + __expf(-2.0f * x)) - 1.0f;
}

// ---------------- targets dtype detection (int32 vs int64) ----------------
__global__ void detect_tok_kernel(const void* __restrict__ tgt) {
    const long long* p = (const long long*)tgt;
    int ok = 1;
    for (int i = 0; i < 16; i++) {
        long long v = p[i];
        if (v < 0 || v >= VOC) ok = 0;
    }
    g_tok64 = ok;
}

// ---------------- one merged weight-packing kernel ----------------
#define N_WHH  (HID * HID)        // 65536
#define N_WIH  (384 * HID)        // 98304
#define N_WENC (HID * HID)        // 65536
#define N_WFC  (HID * VOCP)       // 114688
#define N_PACK (N_WHH + N_WIH + N_WENC + N_WFC)   // 344064

__global__ __launch_bounds__(256) void pack_all(const float* __restrict__ Whh,
                                                const float* __restrict__ Wih,
                                                const float* __restrict__ Wenc,
                                                const float* __restrict__ Wfc) {
    int i = blockIdx.x * 256 + threadIdx.x;
    if (i < N_WHH) {
        int k = i / HID, j = i % HID;
        float4 v;
        v.x = Whh[(0 * HID + j) * HID + k];
        v.y = Whh[(1 * HID + j) * HID + k];
        v.z = Whh[(2 * HID + j) * HID + k];
        v.w = Whh[(3 * HID + j) * HID + k];
        *(float4*)(g_WpackHH + (size_t)i * 4) = v;
        return;
    }
    i -= N_WHH;
    if (i < N_WIH) {
        int e = i / HID, j = i % HID;
        float4 v;
        v.x = Wih[(0 * HID + j) * 384 + e];
        v.y = Wih[(1 * HID + j) * 384 + e];
        v.z = Wih[(2 * HID + j) * 384 + e];
        v.w = Wih[(3 * HID + j) * 384 + e];
        if (e < EMB) *(float4*)(g_WpackIH_E + ((size_t)e * HID + j) * 4) = v;
        else         *(float4*)(g_WpackIH_H + ((size_t)(e - EMB) * HID + j) * 4) = v;
        return;
    }
    i -= N_WIH;
    if (i < N_WENC) {
        int k = i / HID, h = i % HID;
        g_WencT[i] = Wenc[h * HID + k];
        return;
    }
    i -= N_WENC;
    if (i < N_WFC) {
        int k = i / VOCP, v = i % VOCP;
        g_WfcT[i] = (v < VOC) ? Wfc[v * HID + k] : 0.0f;
    }
}

// ------- merged prologue: blocks 0..255  -> enc+encgate for 4 batch rows
//                           blocks 256..665 -> embgate for one vocab row -------
__global__ __launch_bounds__(256) void pre_kernel(const float* __restrict__ eo,
                                                  const float* __restrict__ benc,
                                                  const float* __restrict__ bih,
                                                  const float* __restrict__ bhh,
                                                  const float* __restrict__ emb) {
    __shared__ float xs[4][HID];
    __shared__ float es[4][HID];
    int j = threadIdx.x;
    int bid = blockIdx.x;

    if (bid >= BATCH / 4) {
        // ---- embgate path ----
        int v = bid - BATCH / 4;
        if (j < EMB) xs[0][j] = emb[(size_t)v * EMB + j];
        __syncthreads();
        float4 acc = make_float4(0.f, 0.f, 0.f, 0.f);
        for (int e = 0; e < EMB; e++) {
            float4 w = *(const float4*)(g_WpackIH_E + ((size_t)e * HID + j) * 4);
            float x = xs[0][e];
            acc.x += x * w.x; acc.y += x * w.y;
            acc.z += x * w.z; acc.w += x * w.w;
        }
        *(float4*)(g_embgate + ((size_t)v * HID + j) * 4) = acc;
        return;
    }

    // ---- enc + encgate path ----
    int b0 = bid * 4;
#pragma unroll
    for (int r = 0; r < 4; r++) xs[r][j] = eo[(size_t)(b0 + r) * HID + j];
    __syncthreads();
    {
        float a0 = 0.f, a1 = 0.f, a2 = 0.f, a3 = 0.f;
        for (int k = 0; k < HID; k++) {
            float w = g_WencT[k * HID + j];
            a0 += xs[0][k] * w; a1 += xs[1][k] * w;
            a2 += xs[2][k] * w; a3 += xs[3][k] * w;
        }
        float bb = benc[j];
        es[0][j] = a0 + bb; es[1][j] = a1 + bb;
        es[2][j] = a2 + bb; es[3][j] = a3 + bb;
    }
    __syncthreads();
    float4 acc[4];
#pragma unroll
    for (int r = 0; r < 4; r++) acc[r] = make_float4(0.f, 0.f, 0.f, 0.f);
    for (int h = 0; h < HID; h++) {
        float4 w = *(const float4*)(g_WpackIH_H + ((size_t)h * HID + j) * 4);
#pragma unroll
        for (int r = 0; r < 4; r++) {
            float x = es[r][h];
            acc[r].x += x * w.x; acc[r].y += x * w.y;
            acc[r].z += x * w.z; acc[r].w += x * w.w;
        }
    }
    float4 bias;
    bias.x = bih[0 * HID + j] + bhh[0 * HID + j];
    bias.y = bih[1 * HID + j] + bhh[1 * HID + j];
    bias.z = bih[2 * HID + j] + bhh[2 * HID + j];
    bias.w = bih[3 * HID + j] + bhh[3 * HID + j];
#pragma unroll
    for (int r = 0; r < 4; r++) {
        float4 o = acc[r];
        o.x += bias.x; o.y += bias.y; o.z += bias.z; o.w += bias.w;
        *(float4*)(g_encgate + ((size_t)(b0 + r) * HID + j) * 4) = o;
    }
}

// ---------------- the recurrence: 99 LSTM steps, 8 rows / block, 512 threads ----------------
// SPLIT-K layout: thread = (j in 0..255, kg in {0,1}).
// Each kg half accumulates ALL 8 batch rows over its 128-k half (disjoint
// weight lines -> no duplicated LDG wavefronts), then halves exchange partial
// gate sums via smem and each finishes the epilogue for 4 rows.
__global__ __launch_bounds__(512, 1) void lstm_kernel(const void* __restrict__ tgt) {
    // h duplicated for f32x2: h_dup[k][r*2+{0,1}], r=0..7 -> 16 floats/k (16 KB)
    __shared__ __align__(16) float h_dup[HID * 16];
    // partial-gate exchange: buf[r][j] = ulonglong2 (acc pair) (32 KB)
    __shared__ ulonglong2 buf[8][HID];

    int tid = threadIdx.x;
    int j   = tid & 255;
    int kg  = tid >> 8;          // 0/1: k half
    int b0  = blockIdx.x * 8;
    int lane = tid & 31;
    const int tok64 = g_tok64;
    const long long* t64 = (const long long*)tgt;
    const int*       t32 = (const int*)tgt;

    // epilogue rows for this thread: R = kg*4 + r, r=0..3
    float4 ev[4];
#pragma unroll
    for (int r = 0; r < 4; r++)
        ev[r] = *(const float4*)(g_encgate + ((size_t)(b0 + kg * 4 + r) * HID + j) * 4);

    float c[4] = {0.f, 0.f, 0.f, 0.f};
    for (int i = tid; i < HID * 16; i += 512) h_dup[i] = 0.0f;
    __syncthreads();

    const ulonglong2* Wp = (const ulonglong2*)g_WpackHH + (size_t)kg * 128 * HID;

    for (int t = 0; t < TSTEPS; t++) {
        // tokens for this block's 8 rows: lanes 0..7 load, broadcast by shfl
        int myTok = 0;
        if (lane < 8) {
            size_t idx = (size_t)(b0 + lane) * SEQ + t;
            myTok = tok64 ? (int)t64[idx] : t32[idx];
        }
        int tok[4];
#pragma unroll
        for (int r = 0; r < 4; r++) tok[r] = __shfl_sync(0xffffffffu, myTok, kg * 4 + r);

        // embgate for my 4 epilogue rows (hidden under the k-loop)
        float4 gx[4];
#pragma unroll
        for (int r = 0; r < 4; r++)
            gx[r] = *(const float4*)(g_embgate + ((size_t)tok[r] * HID + j) * 4);

        unsigned long long acc[8][2];
#pragma unroll
        for (int r = 0; r < 8; r++) { acc[r][0] = 0ull; acc[r][1] = 0ull; }

        // partial gates over my k half, all 8 rows
#pragma unroll 4
        for (int kk = 0; kk < 128; kk++) {
            ulonglong2 wv = Wp[kk * HID + j];            // (w_i,w_f),(w_g,w_o)
            const ulonglong2* hp = (const ulonglong2*)(h_dup + (kg * 128 + kk) * 16);
            ulonglong2 h01 = hp[0], h23 = hp[1], h45 = hp[2], h67 = hp[3];
            fma2(acc[0][0], h01.x, wv.x); fma2(acc[0][1], h01.x, wv.y);
            fma2(acc[1][0], h01.y, wv.x); fma2(acc[1][1], h01.y, wv.y);
            fma2(acc[2][0], h23.x, wv.x); fma2(acc[2][1], h23.x, wv.y);
            fma2(acc[3][0], h23.y, wv.x); fma2(acc[3][1], h23.y, wv.y);
            fma2(acc[4][0], h45.x, wv.x); fma2(acc[4][1], h45.x, wv.y);
            fma2(acc[5][0], h45.y, wv.x); fma2(acc[5][1], h45.y, wv.y);
            fma2(acc[6][0], h67.x, wv.x); fma2(acc[6][1], h67.x, wv.y);
            fma2(acc[7][0], h67.y, wv.x); fma2(acc[7][1], h67.y, wv.y);
        }
        __syncthreads();   // all k-loop reads of h_dup complete

        // send the 4 rows the OTHER half finishes: kg=0 -> rows 4..7, kg=1 -> rows 0..3
        {
            int ro = (kg ^ 1) * 4;
#pragma unroll
            for (int r = 0; r < 4; r++) {
                ulonglong2 v; v.x = acc[ro + r][0]; v.y = acc[ro + r][1];
                buf[ro + r][j] = v;
            }
        }
        __syncthreads();

        // combine + epilogue for my 4 rows (R = kg*4 + r)
        float hv[4];
#pragma unroll
        for (int r = 0; r < 4; r++) {
            int R = kg * 4 + r;
            ulonglong2 part = buf[R][j];
            add2(acc[R][0], part.x);
            add2(acc[R][1], part.y);
            float2 if_ = unpack2(acc[R][0]);
            float2 go  = unpack2(acc[R][1]);
            float xi = if_.x + gx[r].x + ev[r].x;
            float xf = if_.y + gx[r].y + ev[r].y;
            float xg = go.x  + gx[r].z + ev[r].z;
            float xo = go.y  + gx[r].w + ev[r].w;
            float ii = sigf(xi), ff = sigf(xf);
            float gg = tanhfast(xg), oo = sigf(xo);
            c[r] = ff * c[r] + ii * gg;
            hv[r] = oo * tanhfast(c[r]);
        }
        // write my 4 rows (duplicated) into h_dup[j][R*2..]: 8 contiguous floats
        {
            float4 w0 = make_float4(hv[0], hv[0], hv[1], hv[1]);
            float4 w1 = make_float4(hv[2], hv[2], hv[3], hv[3]);
            float* base = h_dup + j * 16 + kg * 8;
            *(float4*)(base)     = w0;
            *(float4*)(base + 4) = w1;
#pragma unroll
            for (int r = 0; r < 4; r++)
                g_hs[((size_t)(b0 + kg * 4 + r) * TSTEPS + t) * HID + j] = hv[r];
        }
        __syncthreads();   // h_dup fully updated before next step
    }
}

// ---------------- logits = hs @ W_fc^T + b_fc  (M=101376, N=410, K=256) ----------------
#define GM 128
#define GN 64
#define GK 16
__global__ __launch_bounds__(256) void logits_gemm(const float* __restrict__ bfc,
                                                   float* __restrict__ out) {
    __shared__ __align__(16) float As[GK * GM * 2];  // [kk][m*2] duplicated, 16 KB
    __shared__ __align__(16) float Bs[GK * GN];      // [kk][n], 4 KB
    int tid = threadIdx.x;
    int tx = tid & 15;     // n group (4 cols)
    int ty = tid >> 4;     // m group (8 rows)
    size_t row0 = (size_t)blockIdx.x * GM;
    int n0 = blockIdx.y * GN;

    unsigned long long acc[8][2];
#pragma unroll
    for (int m = 0; m < 8; m++) { acc[m][0] = 0ull; acc[m][1] = 0ull; }

    for (int k0 = 0; k0 < HID; k0 += GK) {
#pragma unroll
        for (int l = 0; l < 2; l++) {
            int idx = tid + l * 256;       // 0..511
            int r  = idx >> 2;             // 0..127
            int kq = idx & 3;              // 0..3
            float4 v = *(const float4*)(g_hs + (row0 + r) * HID + k0 + kq * 4);
            int kk = kq * 4;
            As[(kk + 0) * 2 * GM + r * 2] = v.x; As[(kk + 0) * 2 * GM + r * 2 + 1] = v.x;
            As[(kk + 1) * 2 * GM + r * 2] = v.y; As[(kk + 1) * 2 * GM + r * 2 + 1] = v.y;
            As[(kk + 2) * 2 * GM + r * 2] = v.z; As[(kk + 2) * 2 * GM + r * 2 + 1] = v.z;
            As[(kk + 3) * 2 * GM + r * 2] = v.w; As[(kk + 3) * 2 * GM + r * 2 + 1] = v.w;
        }
        {
            int kk = tid >> 4;
            int nq = tid & 15;
            float4 bv = *(const float4*)(g_WfcT + (size_t)(k0 + kk) * VOCP + n0 + nq * 4);
            *(float4*)(Bs + kk * GN + nq * 4) = bv;
        }
        __syncthreads();
#pragma unroll
        for (int kk = 0; kk < GK; kk++) {
            const ulonglong2* ap = (const ulonglong2*)(As + kk * 2 * GM + ty * 16);
            ulonglong2 a01 = ap[0], a23 = ap[1], a45 = ap[2], a67 = ap[3];
            ulonglong2 bb = *(const ulonglong2*)(Bs + kk * GN + tx * 4);
            fma2(acc[0][0], a01.x, bb.x); fma2(acc[0][1], a01.x, bb.y);
            fma2(acc[1][0], a01.y, bb.x); fma2(acc[1][1], a01.y, bb.y);
            fma2(acc[2][0], a23.x, bb.x); fma2(acc[2][1], a23.x, bb.y);
            fma2(acc[3][0], a23.y, bb.x); fma2(acc[3][1], a23.y, bb.y);
            fma2(acc[4][0], a45.x, bb.x); fma2(acc[4][1], a45.x, bb.y);
            fma2(acc[5][0], a45.y, bb.x); fma2(acc[5][1], a45.y, bb.y);
            fma2(acc[6][0], a67.x, bb.x); fma2(acc[6][1], a67.x, bb.y);
            fma2(acc[7][0], a67.y, bb.x); fma2(acc[7][1], a67.y, bb.y);
        }
        __syncthreads();
    }

    int n = n0 + tx * 4;
    float b0v = (n + 0 < VOC) ? bfc[n + 0] : 0.f;
    float b1v = (n + 1 < VOC) ? bfc[n + 1] : 0.f;
    float b2v = (n + 2 < VOC) ? bfc[n + 2] : 0.f;
    float b3v = (n + 3 < VOC) ? bfc[n + 3] : 0.f;
#pragma unroll
    for (int m = 0; m < 8; m++) {
        size_t row = row0 + (size_t)ty * 8 + m;
        float2 v01 = unpack2(acc[m][0]);
        float2 v23 = unpack2(acc[m][1]);
        float* op = out + row * VOC + n;
        if (n + 0 < VOC) op[0] = v01.x + b0v;
        if (n + 1 < VOC) op[1] = v01.y + b1v;
        if (n + 2 < VOC) op[2] = v23.x + b2v;
        if (n + 3 < VOC) op[3] = v23.y + b3v;
    }
}

// ---------------- launch ----------------
extern "C" void kernel_launch(void* const* d_in, const int* in_sizes, int n_in,
                              void* d_out, int out_size) {
    const float* encoder_out = (const float*)d_in[0];
    const void*  targets     = (const void*)d_in[1];
    const float* emb         = (const float*)d_in[2];
    const float* W_enc       = (const float*)d_in[3];
    const float* b_enc       = (const float*)d_in[4];
    const float* W_ih        = (const float*)d_in[5];
    const float* W_hh        = (const float*)d_in[6];
    const float* b_ih        = (const float*)d_in[7];
    const float* b_hh        = (const float*)d_in[8];
    const float* W_fc        = (const float*)d_in[9];
    const float* b_fc        = (const float*)d_in[10];
    float* out = (float*)d_out;

    detect_tok_kernel<<<1, 1>>>(targets);                                      // 1
    pack_all<<<(N_PACK + 255) / 256, 256>>>(W_hh, W_ih, W_enc, W_fc);          // 2
    pre_kernel<<<BATCH / 4 + VOC, 256>>>(encoder_out, b_enc, b_ih, b_hh, emb); // 3
    lstm_kernel<<<BATCH / 8, 512>>>(targets);                                  // 4
    dim3 grid((BATCH * TSTEPS) / GM, (VOCP + GN - 1) / GN);                    // (792, 7)
    logits_gemm<<<grid, 256>>>(b_fc, out);                                     // 5
}